// round 15
// baseline (speedup 1.0000x reference)
#include <cuda_runtime.h>
#include <cuda_fp16.h>
#include <stdint.h>

#define N_NODES 50000
#define N_EDGES 800000
#define IN_F    256
#define OUT_F   64
#define CAP     128           // bucket capacity per node (avg degree 16)

// Device scratch (no allocs allowed)
__device__ __half g_h[N_NODES * OUT_F];             // 6.4 MB: h = x @ W (fp16)
__device__ int    g_cnt[N_NODES];                   // per-dst edge counts
__device__ uint2  g_bucket[(size_t)N_NODES * CAP];  // 51.2 MB: (src, w_bits)

__device__ __forceinline__ uint32_t f2tf(float f) {
    uint32_t r;
    asm("cvt.rna.tf32.f32 %0, %1;" : "=r"(r) : "f"(f));
    return r;
}
__device__ __forceinline__ void cp16(uint32_t dst, const void* src) {
    asm volatile("cp.async.cg.shared.global [%0], [%1], 16;" :: "r"(dst), "l"(src));
}

// ---------------------------------------------------------------------------
// Kernel 1: h = x @ W via mma.sync tf32, 3-stage cp.async pipeline with true
// 2-tile in-flight depth (round-14 proven, byte-identical).
// ---------------------------------------------------------------------------
#define BM 128
#define BK 16
#define XS_STR 20
#define WS_STR 72
#define STAGES 3

__global__ void __launch_bounds__(256, 3) gemm_kernel(
    const float* __restrict__ x, const float* __restrict__ w)
{
    __shared__ __align__(16) float xs[STAGES][BM][XS_STR];  // A tiles [row][k]
    __shared__ __align__(16) float ws[STAGES][BK][WS_STR];  // W tiles [k][n]

    const int tid  = threadIdx.x;
    const int wid  = tid >> 5;
    const int lane = tid & 31;
    const int wm = wid >> 1;
    const int wn = wid & 1;
    const int g  = lane >> 2;
    const int q  = lane & 3;
    const int block_m = blockIdx.x * BM;

    const int arow = tid >> 2;
    const int akc  = (tid & 3) << 2;
    const int gr0 = min(block_m + arow,      N_NODES - 1);
    const int gr1 = min(block_m + arow + 64, N_NODES - 1);
    const float* xp0 = x + (size_t)gr0 * IN_F + akc;
    const float* xp1 = x + (size_t)gr1 * IN_F + akc;

    const int wk  = tid >> 4;
    const int wn4 = (tid & 15) << 2;
    const float* wp = w + (size_t)wk * OUT_F + wn4;

    const int NKT = IN_F / BK;   // 16

    uint32_t xs_dst[STAGES], ws_dst[STAGES];
    #pragma unroll
    for (int s = 0; s < STAGES; s++) {
        xs_dst[s] = (uint32_t)__cvta_generic_to_shared(&xs[s][arow][akc]);
        ws_dst[s] = (uint32_t)__cvta_generic_to_shared(&ws[s][wk][wn4]);
    }
    const uint32_t xs_row64 = 64 * XS_STR * 4;

    float acc[2][4][4];
    #pragma unroll
    for (int i = 0; i < 2; i++)
        #pragma unroll
        for (int j = 0; j < 4; j++)
            #pragma unroll
            for (int r = 0; r < 4; r++) acc[i][j][r] = 0.f;

    #pragma unroll
    for (int t = 0; t < 2; t++) {
        const int k0 = t * BK;
        cp16(xs_dst[t],            xp0 + k0);
        cp16(xs_dst[t] + xs_row64, xp1 + k0);
        cp16(ws_dst[t],            wp + (size_t)k0 * OUT_F);
        asm volatile("cp.async.commit_group;");
    }

    #pragma unroll 1
    for (int kt = 0; kt < NKT; kt++) {
        __syncthreads();

        if (kt + 2 < NKT) {
            const int nb = (kt + 2) % STAGES;
            const int k0 = (kt + 2) * BK;
            cp16(xs_dst[nb],            xp0 + k0);
            cp16(xs_dst[nb] + xs_row64, xp1 + k0);
            cp16(ws_dst[nb],            wp + (size_t)k0 * OUT_F);
            asm volatile("cp.async.commit_group;");
        }

        if (kt + 2 < NKT)      asm volatile("cp.async.wait_group 2;");
        else if (kt + 1 < NKT) asm volatile("cp.async.wait_group 1;");
        else                   asm volatile("cp.async.wait_group 0;");

        __syncthreads();

        const int buf = kt % STAGES;
        #pragma unroll
        for (int s = 0; s < 2; s++) {
            uint32_t a[2][4], b[4][2];
            #pragma unroll
            for (int i = 0; i < 2; i++) {
                const float* xr  = &xs[buf][wm * 32 + 16 * i + g][8 * s + q];
                const float* xr8 = xr + 8 * XS_STR;
                a[i][0] = f2tf(xr[0]);  a[i][2] = f2tf(xr[4]);
                a[i][1] = f2tf(xr8[0]); a[i][3] = f2tf(xr8[4]);
            }
            #pragma unroll
            for (int j = 0; j < 4; j++) {
                const float* wr = &ws[buf][8 * s + q][wn * 32 + 8 * j + g];
                b[j][0] = f2tf(wr[0]);
                b[j][1] = f2tf(wr[4 * WS_STR]);
            }
            #pragma unroll
            for (int i = 0; i < 2; i++)
                #pragma unroll
                for (int j = 0; j < 4; j++)
                    asm("mma.sync.aligned.m16n8k8.row.col.f32.tf32.tf32.f32 "
                        "{%0,%1,%2,%3}, {%4,%5,%6,%7}, {%8,%9}, {%0,%1,%2,%3};"
                        : "+f"(acc[i][j][0]), "+f"(acc[i][j][1]),
                          "+f"(acc[i][j][2]), "+f"(acc[i][j][3])
                        : "r"(a[i][0]), "r"(a[i][1]), "r"(a[i][2]), "r"(a[i][3]),
                          "r"(b[j][0]), "r"(b[j][1]));
        }
    }

    #pragma unroll
    for (int i = 0; i < 2; i++) {
        const int row = block_m + wm * 32 + 16 * i + g;
        #pragma unroll
        for (int j = 0; j < 4; j++) {
            const int col = wn * 32 + 8 * j + 2 * q;
            if (row < N_NODES)
                *(__half2*)(g_h + (size_t)row * OUT_F + col) =
                    __float22half2_rn(make_float2(acc[i][j][0], acc[i][j][1]));
            if (row + 8 < N_NODES)
                *(__half2*)(g_h + (size_t)(row + 8) * OUT_F + col) =
                    __float22half2_rn(make_float2(acc[i][j][2], acc[i][j][3]));
        }
    }
}

// ---------------------------------------------------------------------------
// Kernel 2: zero the per-node counters
// ---------------------------------------------------------------------------
__global__ void zero_kernel()
{
    const int t = blockIdx.x * blockDim.x + threadIdx.x;
    if (t < N_NODES) g_cnt[t] = 0;
}

// ---------------------------------------------------------------------------
// Kernel 3: reorder — 4 edges per thread, vectorized index loads.
// ---------------------------------------------------------------------------
__global__ void __launch_bounds__(256) reorder_kernel(
    const float* __restrict__ ew, const int* __restrict__ esrc,
    const int* __restrict__ edst)
{
    const int base = (blockIdx.x * blockDim.x + threadIdx.x) * 4;
    if (base >= N_EDGES) return;          // N_EDGES % 4 == 0 -> base+3 in range
    const float4 wv = __ldg((const float4*)(ew + base));
    const int4   sv = __ldg((const int4*)(esrc + base));
    const int4   dv = __ldg((const int4*)(edst + base));
    const int   ds[4] = {dv.x, dv.y, dv.z, dv.w};
    const int   ss[4] = {sv.x, sv.y, sv.z, sv.w};
    const float wf[4] = {wv.x, wv.y, wv.z, wv.w};
    #pragma unroll
    for (int k = 0; k < 4; k++) {
        int pos = atomicAdd(&g_cnt[ds[k]], 1);
        pos = min(pos, CAP - 1);          // safety clamp (statistically unreachable)
        g_bucket[(size_t)ds[k] * CAP + pos] =
            make_uint2((uint32_t)ss[k], __float_as_uint(wf[k]));
    }
}

// ---------------------------------------------------------------------------
// Kernel 4: gather — HALF-WARP per node, SHFL-FREE.
//   Bucket entries read by uniform __ldg (all 16 lanes same address -> one
//   wavefront, L1-resident line); each h-load depends only on its own entry
//   load -> 8 independent depth-2 chains per batch, no MIO shfl traffic.
// ---------------------------------------------------------------------------
__global__ void __launch_bounds__(256) gather_kernel(
    float* __restrict__ out, const float* __restrict__ bias)
{
    const int gwarp = (blockIdx.x * blockDim.x + threadIdx.x) >> 5;
    const int lane  = threadIdx.x & 31;
    const int half  = lane >> 4;            // 0 or 1
    const int hl    = lane & 15;            // lane within half
    const int node  = gwarp * 2 + half;
    if (node >= N_NODES) return;

    const int cnt = min(__ldg(&g_cnt[node]), CAP);
    const uint2* bk = g_bucket + (size_t)node * CAP;

    float acc[4] = {0.f, 0.f, 0.f, 0.f};

    #pragma unroll 1
    for (int base = 0; base < cnt; base += 8) {
        float wv[8];
        uint2 hv[8];
        #pragma unroll
        for (int k = 0; k < 8; k++) {
            const int idx = base + k;
            const uint2 e = __ldg(&bk[min(idx, cnt - 1)]);   // uniform address
            wv[k] = (idx < cnt) ? __uint_as_float(e.y) : 0.f;
            hv[k] = __ldg((const uint2*)(g_h + (size_t)e.x * OUT_F + hl * 4));
        }
        #pragma unroll
        for (int k = 0; k < 8; k++) {
            const float2 h0 = __half22float2(*(const __half2*)&hv[k].x);
            const float2 h1 = __half22float2(*(const __half2*)&hv[k].y);
            acc[0] = fmaf(wv[k], h0.x, acc[0]);
            acc[1] = fmaf(wv[k], h0.y, acc[1]);
            acc[2] = fmaf(wv[k], h1.x, acc[2]);
            acc[3] = fmaf(wv[k], h1.y, acc[3]);
        }
    }

    const float4 b = __ldg((const float4*)(bias + hl * 4));
    float4 r = make_float4(acc[0] + b.x, acc[1] + b.y, acc[2] + b.z, acc[3] + b.w);
    *(float4*)(out + (size_t)node * OUT_F + hl * 4) = r;
}

// ---------------------------------------------------------------------------
// inputs (metadata order): x, weight, bias, edge_weight, edge_src, edge_dst
// ---------------------------------------------------------------------------
extern "C" void kernel_launch(void* const* d_in, const int* in_sizes, int n_in,
                              void* d_out, int out_size)
{
    const float* x      = (const float*)d_in[0];
    const float* weight = (const float*)d_in[1];
    const float* bias   = (const float*)d_in[2];
    const float* ew     = (const float*)d_in[3];
    const int*   esrc   = (const int*)d_in[4];
    const int*   edst   = (const int*)d_in[5];
    float* out = (float*)d_out;

    // 1) reset counters
    zero_kernel<<<(N_NODES + 255) / 256, 256>>>();

    // 2) bucket edges by dst (4 edges per thread)
    {
        const int threads = N_EDGES / 4;
        reorder_kernel<<<(threads + 255) / 256, 256>>>(ew, esrc, edst);
    }

    // 3) h = x @ W   (mma.sync tf32, deep cp.async pipeline)
    gemm_kernel<<<(N_NODES + BM - 1) / BM, 256>>>(x, weight);

    // 4) gather: 2 nodes per warp (half-warp each), shfl-free
    {
        const int nodes_per_block = 2 * (256 / 32);     // 16
        const int grid = (N_NODES + nodes_per_block - 1) / nodes_per_block;
        gather_kernel<<<grid, 256>>>(out, bias);
    }
}

// round 16
// speedup vs baseline: 1.4645x; 1.4645x over previous
#include <cuda_runtime.h>
#include <cuda_fp16.h>
#include <stdint.h>

#define N_NODES 50000
#define N_EDGES 800000
#define IN_F    256
#define OUT_F   64
#define CAP     128           // bucket capacity per node (avg degree 16)

// Device scratch (no allocs allowed)
__device__ __half g_h[N_NODES * OUT_F];             // 6.4 MB: h = x @ W (fp16)
__device__ int    g_cnt[N_NODES];                   // per-dst edge counts
__device__ uint2  g_bucket[(size_t)N_NODES * CAP];  // 51.2 MB: (src, w_bits)

__device__ __forceinline__ uint32_t f2tf(float f) {
    uint32_t r;
    asm("cvt.rna.tf32.f32 %0, %1;" : "=r"(r) : "f"(f));
    return r;
}
__device__ __forceinline__ void cp16(uint32_t dst, const void* src) {
    asm volatile("cp.async.cg.shared.global [%0], [%1], 16;" :: "r"(dst), "l"(src));
}

// ---------------------------------------------------------------------------
// Kernel 1: h = x @ W via mma.sync tf32, 3-stage cp.async pipeline with true
// 2-tile in-flight depth (round-14 proven, byte-identical).
// ---------------------------------------------------------------------------
#define BM 128
#define BK 16
#define XS_STR 20
#define WS_STR 72
#define STAGES 3

__global__ void __launch_bounds__(256, 3) gemm_kernel(
    const float* __restrict__ x, const float* __restrict__ w)
{
    __shared__ __align__(16) float xs[STAGES][BM][XS_STR];  // A tiles [row][k]
    __shared__ __align__(16) float ws[STAGES][BK][WS_STR];  // W tiles [k][n]

    const int tid  = threadIdx.x;
    const int wid  = tid >> 5;
    const int lane = tid & 31;
    const int wm = wid >> 1;
    const int wn = wid & 1;
    const int g  = lane >> 2;
    const int q  = lane & 3;
    const int block_m = blockIdx.x * BM;

    const int arow = tid >> 2;
    const int akc  = (tid & 3) << 2;
    const int gr0 = min(block_m + arow,      N_NODES - 1);
    const int gr1 = min(block_m + arow + 64, N_NODES - 1);
    const float* xp0 = x + (size_t)gr0 * IN_F + akc;
    const float* xp1 = x + (size_t)gr1 * IN_F + akc;

    const int wk  = tid >> 4;
    const int wn4 = (tid & 15) << 2;
    const float* wp = w + (size_t)wk * OUT_F + wn4;

    const int NKT = IN_F / BK;   // 16

    uint32_t xs_dst[STAGES], ws_dst[STAGES];
    #pragma unroll
    for (int s = 0; s < STAGES; s++) {
        xs_dst[s] = (uint32_t)__cvta_generic_to_shared(&xs[s][arow][akc]);
        ws_dst[s] = (uint32_t)__cvta_generic_to_shared(&ws[s][wk][wn4]);
    }
    const uint32_t xs_row64 = 64 * XS_STR * 4;

    float acc[2][4][4];
    #pragma unroll
    for (int i = 0; i < 2; i++)
        #pragma unroll
        for (int j = 0; j < 4; j++)
            #pragma unroll
            for (int r = 0; r < 4; r++) acc[i][j][r] = 0.f;

    #pragma unroll
    for (int t = 0; t < 2; t++) {
        const int k0 = t * BK;
        cp16(xs_dst[t],            xp0 + k0);
        cp16(xs_dst[t] + xs_row64, xp1 + k0);
        cp16(ws_dst[t],            wp + (size_t)k0 * OUT_F);
        asm volatile("cp.async.commit_group;");
    }

    #pragma unroll 1
    for (int kt = 0; kt < NKT; kt++) {
        __syncthreads();

        if (kt + 2 < NKT) {
            const int nb = (kt + 2) % STAGES;
            const int k0 = (kt + 2) * BK;
            cp16(xs_dst[nb],            xp0 + k0);
            cp16(xs_dst[nb] + xs_row64, xp1 + k0);
            cp16(ws_dst[nb],            wp + (size_t)k0 * OUT_F);
            asm volatile("cp.async.commit_group;");
        }

        if (kt + 2 < NKT)      asm volatile("cp.async.wait_group 2;");
        else if (kt + 1 < NKT) asm volatile("cp.async.wait_group 1;");
        else                   asm volatile("cp.async.wait_group 0;");

        __syncthreads();

        const int buf = kt % STAGES;
        #pragma unroll
        for (int s = 0; s < 2; s++) {
            uint32_t a[2][4], b[4][2];
            #pragma unroll
            for (int i = 0; i < 2; i++) {
                const float* xr  = &xs[buf][wm * 32 + 16 * i + g][8 * s + q];
                const float* xr8 = xr + 8 * XS_STR;
                a[i][0] = f2tf(xr[0]);  a[i][2] = f2tf(xr[4]);
                a[i][1] = f2tf(xr8[0]); a[i][3] = f2tf(xr8[4]);
            }
            #pragma unroll
            for (int j = 0; j < 4; j++) {
                const float* wr = &ws[buf][8 * s + q][wn * 32 + 8 * j + g];
                b[j][0] = f2tf(wr[0]);
                b[j][1] = f2tf(wr[4 * WS_STR]);
            }
            #pragma unroll
            for (int i = 0; i < 2; i++)
                #pragma unroll
                for (int j = 0; j < 4; j++)
                    asm("mma.sync.aligned.m16n8k8.row.col.f32.tf32.tf32.f32 "
                        "{%0,%1,%2,%3}, {%4,%5,%6,%7}, {%8,%9}, {%0,%1,%2,%3};"
                        : "+f"(acc[i][j][0]), "+f"(acc[i][j][1]),
                          "+f"(acc[i][j][2]), "+f"(acc[i][j][3])
                        : "r"(a[i][0]), "r"(a[i][1]), "r"(a[i][2]), "r"(a[i][3]),
                          "r"(b[j][0]), "r"(b[j][1]));
        }
    }

    #pragma unroll
    for (int i = 0; i < 2; i++) {
        const int row = block_m + wm * 32 + 16 * i + g;
        #pragma unroll
        for (int j = 0; j < 4; j++) {
            const int col = wn * 32 + 8 * j + 2 * q;
            if (row < N_NODES)
                *(__half2*)(g_h + (size_t)row * OUT_F + col) =
                    __float22half2_rn(make_float2(acc[i][j][0], acc[i][j][1]));
            if (row + 8 < N_NODES)
                *(__half2*)(g_h + (size_t)(row + 8) * OUT_F + col) =
                    __float22half2_rn(make_float2(acc[i][j][2], acc[i][j][3]));
        }
    }
}

// ---------------------------------------------------------------------------
// Kernel 2: zero the per-node counters
// ---------------------------------------------------------------------------
__global__ void zero_kernel()
{
    const int t = blockIdx.x * blockDim.x + threadIdx.x;
    if (t < N_NODES) g_cnt[t] = 0;
}

// ---------------------------------------------------------------------------
// Kernel 3: reorder edges into per-dst buckets (1 edge/thread — proven).
// ---------------------------------------------------------------------------
__global__ void reorder_kernel(const float* __restrict__ ew,
                               const int* __restrict__ esrc,
                               const int* __restrict__ edst)
{
    const int e = blockIdx.x * blockDim.x + threadIdx.x;
    if (e >= N_EDGES) return;
    const int dst = __ldg(&edst[e]);
    const int src = __ldg(&esrc[e]);
    const float w = __ldg(&ew[e]);
    int pos = atomicAdd(&g_cnt[dst], 1);
    pos = min(pos, CAP - 1);        // safety clamp (statistically unreachable)
    g_bucket[(size_t)dst * CAP + pos] = make_uint2((uint32_t)src, __float_as_uint(w));
}

// ---------------------------------------------------------------------------
// Kernel 4: gather — HALF-WARP per node (round-10/14 proven logic), with
// min-blocks hint to lift occupancy (regs 47 -> <=42).
// ---------------------------------------------------------------------------
__global__ void __launch_bounds__(256, 6) gather_kernel(
    float* __restrict__ out, const float* __restrict__ bias)
{
    const int gwarp = (blockIdx.x * blockDim.x + threadIdx.x) >> 5;
    const int lane  = threadIdx.x & 31;
    const int half  = lane >> 4;            // 0 or 1
    const int hl    = lane & 15;            // lane within half
    const int node  = gwarp * 2 + half;
    if (node >= N_NODES) return;

    const unsigned hmask = half ? 0xffff0000u : 0x0000ffffu;
    const int laneoff = half << 4;

    const int cnt = min(__ldg(&g_cnt[node]), CAP);
    const uint2* bk = g_bucket + (size_t)node * CAP;

    float acc[4] = {0.f, 0.f, 0.f, 0.f};

    #pragma unroll 1
    for (int base = 0; base < cnt; base += 16) {
        uint2 ev = (base + hl < cnt) ? __ldg(&bk[base + hl]) : make_uint2(0u, 0u);
        #pragma unroll
        for (int jb = 0; jb < 16; jb += 8) {
            if (base + jb >= cnt) break;      // uniform within the half-warp
            float wv[8];
            uint2 hv[8];
            #pragma unroll
            for (int k = 0; k < 8; k++) {
                const uint32_t s  = __shfl_sync(hmask, ev.x, laneoff + jb + k);
                const uint32_t wb = __shfl_sync(hmask, ev.y, laneoff + jb + k);
                wv[k] = __uint_as_float(wb);
                hv[k] = __ldg((const uint2*)(g_h + (size_t)s * OUT_F + hl * 4));
            }
            #pragma unroll
            for (int k = 0; k < 8; k++) {
                const float2 h0 = __half22float2(*(const __half2*)&hv[k].x);
                const float2 h1 = __half22float2(*(const __half2*)&hv[k].y);
                acc[0] = fmaf(wv[k], h0.x, acc[0]);
                acc[1] = fmaf(wv[k], h0.y, acc[1]);
                acc[2] = fmaf(wv[k], h1.x, acc[2]);
                acc[3] = fmaf(wv[k], h1.y, acc[3]);
            }
        }
    }

    const float4 b = __ldg((const float4*)(bias + hl * 4));
    float4 r = make_float4(acc[0] + b.x, acc[1] + b.y, acc[2] + b.z, acc[3] + b.w);
    *(float4*)(out + (size_t)node * OUT_F + hl * 4) = r;
}

// ---------------------------------------------------------------------------
// inputs (metadata order): x, weight, bias, edge_weight, edge_src, edge_dst
// Launch order: gemm FIRST so its 51 MB x-stream cannot evict the freshly
// written buckets from L2 before the gather reads them.
// ---------------------------------------------------------------------------
extern "C" void kernel_launch(void* const* d_in, const int* in_sizes, int n_in,
                              void* d_out, int out_size)
{
    const float* x      = (const float*)d_in[0];
    const float* weight = (const float*)d_in[1];
    const float* bias   = (const float*)d_in[2];
    const float* ew     = (const float*)d_in[3];
    const int*   esrc   = (const int*)d_in[4];
    const int*   edst   = (const int*)d_in[5];
    float* out = (float*)d_out;

    // 1) h = x @ W   (mma.sync tf32, deep cp.async pipeline)
    gemm_kernel<<<(N_NODES + BM - 1) / BM, 256>>>(x, weight);

    // 2) reset counters (right before reorder -> g_cnt lines L2-hot)
    zero_kernel<<<(N_NODES + 255) / 256, 256>>>();

    // 3) bucket edges by dst (bucket lines stay L2-hot for the gather)
    reorder_kernel<<<(N_EDGES + 255) / 256, 256>>>(ew, esrc, edst);

    // 4) gather: 2 nodes per warp (half-warp each)
    {
        const int nodes_per_block = 2 * (256 / 32);     // 16
        const int grid = (N_NODES + nodes_per_block - 1) / nodes_per_block;
        gather_kernel<<<grid, 256>>>(out, bias);
    }
}

// round 17
// speedup vs baseline: 1.5207x; 1.0384x over previous
#include <cuda_runtime.h>
#include <cuda_fp16.h>
#include <stdint.h>

#define N_NODES 50000
#define N_EDGES 800000
#define IN_F    256
#define OUT_F   64
#define CAP     128           // bucket capacity per node (avg degree 16)

// Device scratch (no allocs allowed)
__device__ __half    g_h[N_NODES * OUT_F];            // 6.4 MB: h = x @ W (fp16)
__device__ int       g_cnt[N_NODES];                  // per-dst edge counts
__device__ uint32_t  g_bucket[(size_t)N_NODES * CAP]; // 25.6 MB: (src<<16 | half(w))

__device__ __forceinline__ uint32_t f2tf(float f) {
    uint32_t r;
    asm("cvt.rna.tf32.f32 %0, %1;" : "=r"(r) : "f"(f));
    return r;
}
__device__ __forceinline__ void cp16(uint32_t dst, const void* src) {
    asm volatile("cp.async.cg.shared.global [%0], [%1], 16;" :: "r"(dst), "l"(src));
}

// ---------------------------------------------------------------------------
// Kernel 1: h = x @ W via mma.sync tf32, 3-stage cp.async pipeline with true
// 2-tile in-flight depth (round-14 proven, byte-identical).
// ---------------------------------------------------------------------------
#define BM 128
#define BK 16
#define XS_STR 20
#define WS_STR 72
#define STAGES 3

__global__ void __launch_bounds__(256, 3) gemm_kernel(
    const float* __restrict__ x, const float* __restrict__ w)
{
    __shared__ __align__(16) float xs[STAGES][BM][XS_STR];  // A tiles [row][k]
    __shared__ __align__(16) float ws[STAGES][BK][WS_STR];  // W tiles [k][n]

    const int tid  = threadIdx.x;
    const int wid  = tid >> 5;
    const int lane = tid & 31;
    const int wm = wid >> 1;
    const int wn = wid & 1;
    const int g  = lane >> 2;
    const int q  = lane & 3;
    const int block_m = blockIdx.x * BM;

    const int arow = tid >> 2;
    const int akc  = (tid & 3) << 2;
    const int gr0 = min(block_m + arow,      N_NODES - 1);
    const int gr1 = min(block_m + arow + 64, N_NODES - 1);
    const float* xp0 = x + (size_t)gr0 * IN_F + akc;
    const float* xp1 = x + (size_t)gr1 * IN_F + akc;

    const int wk  = tid >> 4;
    const int wn4 = (tid & 15) << 2;
    const float* wp = w + (size_t)wk * OUT_F + wn4;

    const int NKT = IN_F / BK;   // 16

    uint32_t xs_dst[STAGES], ws_dst[STAGES];
    #pragma unroll
    for (int s = 0; s < STAGES; s++) {
        xs_dst[s] = (uint32_t)__cvta_generic_to_shared(&xs[s][arow][akc]);
        ws_dst[s] = (uint32_t)__cvta_generic_to_shared(&ws[s][wk][wn4]);
    }
    const uint32_t xs_row64 = 64 * XS_STR * 4;

    float acc[2][4][4];
    #pragma unroll
    for (int i = 0; i < 2; i++)
        #pragma unroll
        for (int j = 0; j < 4; j++)
            #pragma unroll
            for (int r = 0; r < 4; r++) acc[i][j][r] = 0.f;

    #pragma unroll
    for (int t = 0; t < 2; t++) {
        const int k0 = t * BK;
        cp16(xs_dst[t],            xp0 + k0);
        cp16(xs_dst[t] + xs_row64, xp1 + k0);
        cp16(ws_dst[t],            wp + (size_t)k0 * OUT_F);
        asm volatile("cp.async.commit_group;");
    }

    #pragma unroll 1
    for (int kt = 0; kt < NKT; kt++) {
        __syncthreads();

        if (kt + 2 < NKT) {
            const int nb = (kt + 2) % STAGES;
            const int k0 = (kt + 2) * BK;
            cp16(xs_dst[nb],            xp0 + k0);
            cp16(xs_dst[nb] + xs_row64, xp1 + k0);
            cp16(ws_dst[nb],            wp + (size_t)k0 * OUT_F);
            asm volatile("cp.async.commit_group;");
        }

        if (kt + 2 < NKT)      asm volatile("cp.async.wait_group 2;");
        else if (kt + 1 < NKT) asm volatile("cp.async.wait_group 1;");
        else                   asm volatile("cp.async.wait_group 0;");

        __syncthreads();

        const int buf = kt % STAGES;
        #pragma unroll
        for (int s = 0; s < 2; s++) {
            uint32_t a[2][4], b[4][2];
            #pragma unroll
            for (int i = 0; i < 2; i++) {
                const float* xr  = &xs[buf][wm * 32 + 16 * i + g][8 * s + q];
                const float* xr8 = xr + 8 * XS_STR;
                a[i][0] = f2tf(xr[0]);  a[i][2] = f2tf(xr[4]);
                a[i][1] = f2tf(xr8[0]); a[i][3] = f2tf(xr8[4]);
            }
            #pragma unroll
            for (int j = 0; j < 4; j++) {
                const float* wr = &ws[buf][8 * s + q][wn * 32 + 8 * j + g];
                b[j][0] = f2tf(wr[0]);
                b[j][1] = f2tf(wr[4 * WS_STR]);
            }
            #pragma unroll
            for (int i = 0; i < 2; i++)
                #pragma unroll
                for (int j = 0; j < 4; j++)
                    asm("mma.sync.aligned.m16n8k8.row.col.f32.tf32.tf32.f32 "
                        "{%0,%1,%2,%3}, {%4,%5,%6,%7}, {%8,%9}, {%0,%1,%2,%3};"
                        : "+f"(acc[i][j][0]), "+f"(acc[i][j][1]),
                          "+f"(acc[i][j][2]), "+f"(acc[i][j][3])
                        : "r"(a[i][0]), "r"(a[i][1]), "r"(a[i][2]), "r"(a[i][3]),
                          "r"(b[j][0]), "r"(b[j][1]));
        }
    }

    #pragma unroll
    for (int i = 0; i < 2; i++) {
        const int row = block_m + wm * 32 + 16 * i + g;
        #pragma unroll
        for (int j = 0; j < 4; j++) {
            const int col = wn * 32 + 8 * j + 2 * q;
            if (row < N_NODES)
                *(__half2*)(g_h + (size_t)row * OUT_F + col) =
                    __float22half2_rn(make_float2(acc[i][j][0], acc[i][j][1]));
            if (row + 8 < N_NODES)
                *(__half2*)(g_h + (size_t)(row + 8) * OUT_F + col) =
                    __float22half2_rn(make_float2(acc[i][j][2], acc[i][j][3]));
        }
    }
}

// ---------------------------------------------------------------------------
// Kernel 2: zero the per-node counters
// ---------------------------------------------------------------------------
__global__ void zero_kernel()
{
    const int t = blockIdx.x * blockDim.x + threadIdx.x;
    if (t < N_NODES) g_cnt[t] = 0;
}

// ---------------------------------------------------------------------------
// Kernel 3: reorder — bucket[dst][i] = (src<<16) | half(w).  1 edge/thread.
// ---------------------------------------------------------------------------
__global__ void reorder_kernel(const float* __restrict__ ew,
                               const int* __restrict__ esrc,
                               const int* __restrict__ edst)
{
    const int e = blockIdx.x * blockDim.x + threadIdx.x;
    if (e >= N_EDGES) return;
    const int dst = __ldg(&edst[e]);
    const int src = __ldg(&esrc[e]);
    const float w = __ldg(&ew[e]);
    int pos = atomicAdd(&g_cnt[dst], 1);
    pos = min(pos, CAP - 1);        // safety clamp (statistically unreachable)
    const uint32_t packed = ((uint32_t)src << 16)
                          | (uint32_t)__half_as_ushort(__float2half_rn(w));
    g_bucket[(size_t)dst * CAP + pos] = packed;
}

// ---------------------------------------------------------------------------
// Kernel 4: gather — HALF-WARP per node, packed 4-B bucket entries:
//   1 shfl per edge (was 2), half the bucket bytes. Zero-fill gives w=0.
// ---------------------------------------------------------------------------
__global__ void __launch_bounds__(256) gather_kernel(
    float* __restrict__ out, const float* __restrict__ bias)
{
    const int gwarp = (blockIdx.x * blockDim.x + threadIdx.x) >> 5;
    const int lane  = threadIdx.x & 31;
    const int half_ = lane >> 4;            // 0 or 1
    const int hl    = lane & 15;            // lane within half
    const int node  = gwarp * 2 + half_;
    if (node >= N_NODES) return;

    const unsigned hmask = half_ ? 0xffff0000u : 0x0000ffffu;
    const int laneoff = half_ << 4;

    const int cnt = min(__ldg(&g_cnt[node]), CAP);
    const uint32_t* bk = g_bucket + (size_t)node * CAP;

    float acc[4] = {0.f, 0.f, 0.f, 0.f};

    #pragma unroll 1
    for (int base = 0; base < cnt; base += 16) {
        uint32_t ev = (base + hl < cnt) ? __ldg(&bk[base + hl]) : 0u;
        #pragma unroll
        for (int jb = 0; jb < 16; jb += 8) {
            if (base + jb >= cnt) break;      // uniform within the half-warp
            float wv[8];
            uint2 hv[8];
            #pragma unroll
            for (int k = 0; k < 8; k++) {
                const uint32_t e = __shfl_sync(hmask, ev, laneoff + jb + k);
                wv[k] = __half2float(__ushort_as_half((unsigned short)(e & 0xffffu)));
                hv[k] = __ldg((const uint2*)(g_h + (size_t)(e >> 16) * OUT_F + hl * 4));
            }
            #pragma unroll
            for (int k = 0; k < 8; k++) {
                const float2 h0 = __half22float2(*(const __half2*)&hv[k].x);
                const float2 h1 = __half22float2(*(const __half2*)&hv[k].y);
                acc[0] = fmaf(wv[k], h0.x, acc[0]);
                acc[1] = fmaf(wv[k], h0.y, acc[1]);
                acc[2] = fmaf(wv[k], h1.x, acc[2]);
                acc[3] = fmaf(wv[k], h1.y, acc[3]);
            }
        }
    }

    const float4 b = __ldg((const float4*)(bias + hl * 4));
    float4 r = make_float4(acc[0] + b.x, acc[1] + b.y, acc[2] + b.z, acc[3] + b.w);
    *(float4*)(out + (size_t)node * OUT_F + hl * 4) = r;
}

// ---------------------------------------------------------------------------
// inputs (metadata order): x, weight, bias, edge_weight, edge_src, edge_dst
// ---------------------------------------------------------------------------
extern "C" void kernel_launch(void* const* d_in, const int* in_sizes, int n_in,
                              void* d_out, int out_size)
{
    const float* x      = (const float*)d_in[0];
    const float* weight = (const float*)d_in[1];
    const float* bias   = (const float*)d_in[2];
    const float* ew     = (const float*)d_in[3];
    const int*   esrc   = (const int*)d_in[4];
    const int*   edst   = (const int*)d_in[5];
    float* out = (float*)d_out;

    // 1) reset counters
    zero_kernel<<<(N_NODES + 255) / 256, 256>>>();

    // 2) bucket edges by dst (packed 4-B entries)
    reorder_kernel<<<(N_EDGES + 255) / 256, 256>>>(ew, esrc, edst);

    // 3) h = x @ W   (mma.sync tf32, deep cp.async pipeline)
    gemm_kernel<<<(N_NODES + BM - 1) / BM, 256>>>(x, weight);

    // 4) gather: 2 nodes per warp (half-warp each)
    {
        const int nodes_per_block = 2 * (256 / 32);     // 16
        const int grid = (N_NODES + nodes_per_block - 1) / nodes_per_block;
        gather_kernel<<<grid, 256>>>(out, bias);
    }
}